// round 11
// baseline (speedup 1.0000x reference)
#include <cuda_runtime.h>
#include <cstdint>

#define B_   32
#define L_   256
#define T_   1600
#define C_   40
#define PADM 1.0e12f

// ---------------- scratch (__device__ globals; no allocation allowed) ----------------
__device__ __align__(16) float g_coefA[B_ * C_ * 2 * L_];   // invvar, duplicated pairs
__device__ __align__(16) float g_coefB[B_ * C_ * 2 * L_];   // mu*invvar, duplicated pairs
__device__ __align__(16) float g_t3 [B_ * L_];
__device__ __align__(16) float g_mlv[B_ * L_];

// ---------------- packed f32x2 helpers (sm_103a) ----------------
__device__ __forceinline__ unsigned long long pack2(float lo, float hi) {
    unsigned long long r;
    asm("mov.b64 %0, {%1,%2};" : "=l"(r) : "f"(lo), "f"(hi));
    return r;
}
#define FFMA2_ACC(d, a, b) \
    asm("fma.rn.f32x2 %0, %1, %2, %0;" : "+l"(d) : "l"(a), "l"(b))
#define FFMA2(d, a, b, c) \
    asm("fma.rn.f32x2 %0, %1, %2, %3;" : "=l"(d) : "l"(a), "l"(b), "l"(c))
#define ADD2(d, a, b) \
    asm("add.rn.f32x2 %0, %1, %2;" : "=l"(d) : "l"(a), "l"(b))

// volatile shared accessors
__device__ __forceinline__ uint2 ldsv2v(unsigned a) {
    uint2 r;
    asm volatile("ld.volatile.shared.v2.b32 {%0,%1},[%2];"
                 : "=r"(r.x), "=r"(r.y) : "r"(a));
    return r;
}
__device__ __forceinline__ void stsv2v(unsigned a, float x, float y) {
    asm volatile("st.volatile.shared.v2.b32 [%0],{%1,%2};"
                 :: "r"(a), "r"(__float_as_uint(x)), "r"(__float_as_uint(y)));
}
__device__ __forceinline__ int ldsv1v(unsigned a) {
    int r;
    asm volatile("ld.volatile.shared.b32 %0,[%1];" : "=r"(r) : "r"(a));
    return r;
}
__device__ __forceinline__ void stsv1v(unsigned a, int v) {
    asm volatile("st.volatile.shared.b32 [%0],%1;" :: "r"(a), "r"(v));
}

// ---------------- K0: per-(b,l) coefficients ----------------
__global__ void k0_coef(const float* __restrict__ mu_logvar) {
    int idx = blockIdx.x * 128 + threadIdx.x;          // 0 .. B*L-1
    int b = idx >> 8;
    int l = idx & (L_ - 1);
    const float* row = mu_logvar + (size_t)idx * (2 * C_);
    float* A  = g_coefA + (size_t)b * C_ * 2 * L_ + 2 * l;
    float* Bc = g_coefB + (size_t)b * C_ * 2 * L_ + 2 * l;
    float t3 = 0.f, slv = 0.f;
    for (int c = 0; c < C_; c++) {
        float mu = row[c];
        float lv = row[C_ + c];
        float iv = expf(-lv);
        float miv = mu * iv;
        A [c * 2 * L_]     = iv;
        A [c * 2 * L_ + 1] = iv;
        Bc[c * 2 * L_]     = miv;
        Bc[c * 2 * L_ + 1] = miv;
        t3 = fmaf(mu, miv, t3);
        slv += lv;
    }
    g_t3 [idx] = t3;
    g_mlv[idx] = slv * (1.0f / C_);
}

// ---------------- Kz: zero the alignment output region ----------------
__global__ void kz_zero(float4* __restrict__ p, int n4) {
    int i = blockIdx.x * blockDim.x + threadIdx.x;
    int stride = gridDim.x * blockDim.x;
    float4 z = make_float4(0.f, 0.f, 0.f, 0.f);
    for (; i < n4; i += stride) p[i] = z;
}

// ---------------- K1: lp[b][l][t] via packed FFMA2 GEMM ----------------
__global__ __launch_bounds__(256) void k1_lp(const float* __restrict__ z,
                                             float* __restrict__ lp_out) {
    __shared__ __align__(16) float zs [C_][64];
    __shared__ __align__(16) float z2s[C_][64];
    int b  = blockIdx.z;
    int l0 = blockIdx.y * 128;
    int t0 = blockIdx.x * 64;
    int tid = threadIdx.x;

    const float* zb = z + (size_t)b * C_ * T_ + t0;
    for (int i = tid; i < C_ * 64; i += 256) {
        int c = i >> 6, j = i & 63;
        float v = zb[(size_t)c * T_ + j];
        zs [c][j] = v;
        z2s[c][j] = v * v;
    }
    __syncthreads();

    int lg = tid >> 3, tg = tid & 7;
    int lbase = l0 + lg * 4;

    unsigned long long s1[4][4], s2[4][4];
#pragma unroll
    for (int r = 0; r < 4; r++)
#pragma unroll
        for (int j = 0; j < 4; j++) { s1[r][j] = 0ull; s2[r][j] = 0ull; }

    const float* cA = g_coefA + (size_t)b * C_ * 2 * L_ + 2 * lbase;
    const float* cB = g_coefB + (size_t)b * C_ * 2 * L_ + 2 * lbase;

#pragma unroll 2
    for (int c = 0; c < C_; c++) {
        ulonglong2 aL = *(const ulonglong2*)(cA + (size_t)c * 2 * L_);
        ulonglong2 aH = *(const ulonglong2*)(cA + (size_t)c * 2 * L_ + 4);
        ulonglong2 bL = *(const ulonglong2*)(cB + (size_t)c * 2 * L_);
        ulonglong2 bH = *(const ulonglong2*)(cB + (size_t)c * 2 * L_ + 4);
        unsigned long long ar[4] = {aL.x, aL.y, aH.x, aH.y};
        unsigned long long br[4] = {bL.x, bL.y, bH.x, bH.y};
        ulonglong2 q0 = *(const ulonglong2*)&z2s[c][tg * 8];
        ulonglong2 q1 = *(const ulonglong2*)&z2s[c][tg * 8 + 4];
        ulonglong2 w0 = *(const ulonglong2*)&zs [c][tg * 8];
        ulonglong2 w1 = *(const ulonglong2*)&zs [c][tg * 8 + 4];
        unsigned long long z2p[4] = {q0.x, q0.y, q1.x, q1.y};
        unsigned long long zp [4] = {w0.x, w0.y, w1.x, w1.y};
#pragma unroll
        for (int r = 0; r < 4; r++) {
#pragma unroll
            for (int j = 0; j < 4; j++) {
                FFMA2_ACC(s1[r][j], ar[r], z2p[j]);
                FFMA2_ACC(s2[r][j], br[r], zp[j]);
            }
        }
    }

    float4 t34 = *(const float4*)(g_t3  + b * L_ + lbase);
    float4 mv4 = *(const float4*)(g_mlv + b * L_ + lbase);
    float t3a[4] = {t34.x, t34.y, t34.z, t34.w};
    float mva[4] = {mv4.x, mv4.y, mv4.z, mv4.w};
    unsigned long long m2 = pack2(-2.0f, -2.0f);
    unsigned long long c1 = pack2(-0.0125f, -0.0125f);   // -0.5/C
#pragma unroll
    for (int r = 0; r < 4; r++) {
        unsigned long long tp = pack2(t3a[r], t3a[r]);
        unsigned long long dp = pack2(-0.5f * mva[r], -0.5f * mva[r]);
        unsigned long long o[4];
#pragma unroll
        for (int j = 0; j < 4; j++) {
            unsigned long long mse;
            FFMA2(mse, s2[r][j], m2, s1[r][j]);   // s1 - 2*s2
            ADD2(mse, mse, tp);                   // + t3
            FFMA2(o[j], mse, c1, dp);             // *(-1/80) + (-0.5*mlv)
        }
        float* orow = lp_out + ((size_t)b * L_ + lbase + r) * T_ + t0 + tg * 8;
        ((ulonglong2*)orow)[0] = make_ulonglong2(o[0], o[1]);
        ((ulonglong2*)orow)[1] = make_ulonglong2(o[2], o[3]);
    }
}

// ---------------- K2: branchless 8-warp DP (per-lane bits, addr-select publish) ----
// smem layout (bytes):
//   [0, 51200)         D2[50][256]  per-lane 32-column decision bit words
//   [51200, 153600)    mailbox: 8 warps x 1600 slots x 8B {an, bn}
//   [153600, 166400)   b0h2[1600] float2 (.y = beta[l=0] history)
//   [166400, 172800)   path[1600]
//   [172800, 172832)   prog[8]
//   [172832, 172836)   prog dummy for warp0 (INT_MAX)
//   [172840, 172848)   slot dummy for warp0 ({-PADM,-PADM})
//   [172848, 174896)   dummy sink (256 x 8B)
#define SMB_D2    0
#define SMB_MB    51200
#define SMB_B0H   153600
#define SMB_PATH  166400
#define SMB_PROG  172800
#define SMB_PROGD 172832
#define SMB_SLOTD 172840
#define SMB_DUMMY 172848
#define SMB_TOT   174896

__device__ __forceinline__ void dstep(int t, int sh, float lpv,
                                      float pre_a, float pre_b, int lane0,
                                      float& a, float& bt, unsigned& acc,
                                      float& lossv, int mlm1,
                                      unsigned pubaddr, unsigned pubstride) {
    float sa = __shfl_up_sync(0xffffffffu, a, 1);
    float sb = __shfl_up_sync(0xffffffffu, bt, 1);
    float am = lane0 ? pre_a : sa;
    float bm = lane0 ? pre_b : sb;
    acc |= (bm > bt) ? (1u << sh) : 0u;
    float d = a - am;
    float m = fmaxf(a, am);
    float an = m + __logf(1.0f + __expf(-fabsf(d))) + (lpv + 1e-7f);
    float bn = fmaxf(bt, bm) + lpv;
    lossv = (t == mlm1) ? an : lossv;
    stsv2v(pubaddr + (unsigned)t * pubstride, an, bn);
    a = an; bt = bn;
}

__global__ __launch_bounds__(256, 1) void k2_dp(const float* __restrict__ lp,
                                                const int* __restrict__ tlen,
                                                const int* __restrict__ mlen,
                                                float* __restrict__ out_loss,
                                                float* __restrict__ out_align) {
    extern __shared__ unsigned char smraw[];
    unsigned* D2 = (unsigned*)smraw;
    int* path    = (int*)(smraw + SMB_PATH);
    unsigned smbase = (unsigned)__cvta_generic_to_shared(smraw);

    int b = blockIdx.x;
    int l = threadIdx.x;
    int w = l >> 5, lane = l & 31;
    int lane0 = (lane == 0);
    int ml = mlen[b], tl = tlen[b];
    int mlm1 = ml - 1, tlm1 = tl - 1;
    const float* p = lp + ((size_t)b * L_ + l) * T_;

    unsigned mb = smbase + SMB_MB;
    unsigned mb_self = mb + (unsigned)w * 12800u;
    unsigned mb_src  = w ? (mb + (unsigned)(w - 1) * 12800u) : (smbase + SMB_SLOTD);
    unsigned srcmul  = w ? 8u : 0u;
    unsigned prog_srcaddr = w ? (smbase + SMB_PROG + (unsigned)(w - 1) * 4u)
                              : (smbase + SMB_PROGD);
    unsigned pubaddr, pubstride;
    if (lane == 31)      { pubaddr = mb_self;             pubstride = 8u; }
    else if (l == 0)     { pubaddr = smbase + SMB_B0H;    pubstride = 8u; }
    else                 { pubaddr = smbase + SMB_DUMMY + (unsigned)l * 8u; pubstride = 0u; }
    unsigned progpub = (lane == 31) ? (smbase + SMB_PROG + (unsigned)w * 4u)
                                    : (smbase + SMB_DUMMY + (unsigned)l * 8u);

    if (l == 0) {
        stsv1v(smbase + SMB_PROGD, 0x7FFFFFFF);
        stsv2v(smbase + SMB_SLOTD, -PADM, -PADM);
    }

    float4 q0 = *(const float4*)p;             // lp[t=0..3]
    float a  = (l == 0) ? q0.x : -PADM;
    float bt = a;
    stsv2v(pubaddr, a, bt);                    // slot 0 / b0h2[0] / dummy
    stsv1v(progpub, 0);
    __syncthreads();

    unsigned acc = 0;
    float lossv = 0.f;
    int pc = w ? 0 : 0x7FFFFFFF;

    float4 vc = *(const float4*)(p + 4);       // quad for k=1
    float4 vn = *(const float4*)(p + 8);       // quad for k=2

    // ---- peel k=0: t = 1,2,3 (cols 0,1,2) ----
    {
        if (pc < 2) { do { pc = ldsv1v(prog_srcaddr); } while (pc < 2); }
        uint2 s0 = ldsv2v(mb_src + 0u * srcmul);
        uint2 s1 = ldsv2v(mb_src + 1u * srcmul);
        uint2 s2 = ldsv2v(mb_src + 2u * srcmul);
        dstep(1, 0, q0.y, __uint_as_float(s0.x), __uint_as_float(s0.y), lane0,
              a, bt, acc, lossv, mlm1, pubaddr, pubstride);
        dstep(2, 1, q0.z, __uint_as_float(s1.x), __uint_as_float(s1.y), lane0,
              a, bt, acc, lossv, mlm1, pubaddr, pubstride);
        dstep(3, 2, q0.w, __uint_as_float(s2.x), __uint_as_float(s2.y), lane0,
              a, bt, acc, lossv, mlm1, pubaddr, pubstride);
        stsv1v(progpub, 3);
    }

    // ---- main: m = 0..48, k = 8m+1 .. 8m+8, t = 32m+4 .. 32m+35 ----
    for (int m = 0; m < 49; m++) {
#pragma unroll
        for (int g = 0; g < 8; g++) {
            int k = 8 * m + 1 + g;
            float4 vf = *(const float4*)(p + 4 * (k + 2));   // k+2 <= 394 < 400
            int need = 4 * k + 2;
            if (pc < need) { do { pc = ldsv1v(prog_srcaddr); } while (pc < need); }
            uint2 s0 = ldsv2v(mb_src + (unsigned)(4 * k - 1) * srcmul);
            uint2 s1 = ldsv2v(mb_src + (unsigned)(4 * k    ) * srcmul);
            uint2 s2 = ldsv2v(mb_src + (unsigned)(4 * k + 1) * srcmul);
            uint2 s3 = ldsv2v(mb_src + (unsigned)(4 * k + 2) * srcmul);
            int t0 = 4 * k;
            dstep(t0,     (3 + 4 * g    ) & 31, vc.x, __uint_as_float(s0.x),
                  __uint_as_float(s0.y), lane0, a, bt, acc, lossv, mlm1, pubaddr, pubstride);
            if (g == 7) { D2[m * 256 + l] = acc; acc = 0; }    // col 32m+31 flushed
            dstep(t0 + 1, (4 + 4 * g    ) & 31, vc.y, __uint_as_float(s1.x),
                  __uint_as_float(s1.y), lane0, a, bt, acc, lossv, mlm1, pubaddr, pubstride);
            dstep(t0 + 2, (5 + 4 * g    ) & 31, vc.z, __uint_as_float(s2.x),
                  __uint_as_float(s2.y), lane0, a, bt, acc, lossv, mlm1, pubaddr, pubstride);
            dstep(t0 + 3, (6 + 4 * g    ) & 31, vc.w, __uint_as_float(s3.x),
                  __uint_as_float(s3.y), lane0, a, bt, acc, lossv, mlm1, pubaddr, pubstride);
            stsv1v(progpub, 4 * k + 3);
            vc = vn; vn = vf;
        }
    }

    // ---- tail: k = 393..399, t = 1572..1599 ----
    for (int k = 393; k <= 399; k++) {
        float4 vf = (k <= 397) ? *(const float4*)(p + 4 * (k + 2)) : vc;
        int need = 4 * k + 2;
        if (pc < need) { do { pc = ldsv1v(prog_srcaddr); } while (pc < need); }
        uint2 s0 = ldsv2v(mb_src + (unsigned)(4 * k - 1) * srcmul);
        uint2 s1 = ldsv2v(mb_src + (unsigned)(4 * k    ) * srcmul);
        uint2 s2 = ldsv2v(mb_src + (unsigned)(4 * k + 1) * srcmul);
        uint2 s3 = ldsv2v(mb_src + (unsigned)(4 * k + 2) * srcmul);
        int t0 = 4 * k;
        dstep(t0,     (t0 - 1) & 31, vc.x, __uint_as_float(s0.x),
              __uint_as_float(s0.y), lane0, a, bt, acc, lossv, mlm1, pubaddr, pubstride);
        dstep(t0 + 1, (t0    ) & 31, vc.y, __uint_as_float(s1.x),
              __uint_as_float(s1.y), lane0, a, bt, acc, lossv, mlm1, pubaddr, pubstride);
        dstep(t0 + 2, (t0 + 1) & 31, vc.z, __uint_as_float(s2.x),
              __uint_as_float(s2.y), lane0, a, bt, acc, lossv, mlm1, pubaddr, pubstride);
        dstep(t0 + 3, (t0 + 2) & 31, vc.w, __uint_as_float(s3.x),
              __uint_as_float(s3.y), lane0, a, bt, acc, lossv, mlm1, pubaddr, pubstride);
        stsv1v(progpub, 4 * k + 3);
        vc = vn; vn = vf;
    }

    // ---- final column c = T-1 = 1599 ----
    {
        if (pc < T_ - 1) { do { pc = ldsv1v(prog_srcaddr); } while (pc < T_ - 1); }
        uint2 s = ldsv2v(mb_src + (unsigned)(T_ - 1) * srcmul);
        float sb = __shfl_up_sync(0xffffffffu, bt, 1);
        float bm = lane0 ? __uint_as_float(s.y) : sb;
        acc |= (bm > bt) ? (1u << 31) : 0u;
        D2[49 * 256 + l] = acc;
    }
    if (l == tlm1) out_loss[b] = -lossv / (float)ml;
    __syncthreads();

    // ---- wrap fixup: row-0 bits = (beta[255,c] > beta[0,c]) ----
    if (l < 50) {
        const float2* mbf7 = (const float2*)(smraw + SMB_MB + 7 * 12800);
        const float2* b0f  = (const float2*)(smraw + SMB_B0H);
        unsigned wv = 0;
#pragma unroll 4
        for (int c2 = 0; c2 < 32; c2++) {
            int c = l * 32 + c2;
            wv |= (mbf7[c].y > b0f[c].y) ? (1u << c2) : 0u;
        }
        D2[l * 256] = wv;
    }
    __syncthreads();

    // ---- serial backtrack on D2 with 2-word sliding window ----
    if (l == 0) {
        int r = tlm1;
        path[0] = r;
        int c = mlm1 - 1;
        int k = 1;
        int g = c >> 5;
        unsigned w0 = D2[g * 256 + r];
        unsigned w1 = D2[g * 256 + ((r - 1) & 255)];
        while (k <= mlm1) {
            int bit = (w0 >> (c & 31)) & 1;
            r -= bit;
            path[k++] = r;
            c -= 1;
            if (r < 0) break;
            if (bit) { w0 = w1; w1 = D2[g * 256 + ((r - 1) & 255)]; }
            if ((c & 31) == 31) {
                g = c >> 5;
                w0 = D2[g * 256 + r];
                w1 = D2[g * 256 + ((r - 1) & 255)];
            }
        }
        for (; k <= mlm1; k++) path[k] = -1;   // rows = -1 is absorbing
    }
    __syncthreads();

    // ---- one-hot writes: final[t] = onehot(path[ml-1-t]) for t < ml ----
    size_t abase = (size_t)b * T_ * L_;
    for (int t = l; t < ml; t += 256) {
        int r = path[mlm1 - t];
        if (r >= 0) out_align[abase + (size_t)t * L_ + r] = 1.0f;
    }
}

// ---------------- launch ----------------
extern "C" void kernel_launch(void* const* d_in, const int* in_sizes, int n_in,
                              void* d_out, int out_size) {
    const float* mu_logvar = (const float*)d_in[0];   // [B, L, 2C]
    const float* z         = (const float*)d_in[1];   // [B, C, T]
    const int*   tlen      = (const int*)d_in[2];     // [B]
    const int*   mlen      = (const int*)d_in[3];     // [B]

    float* out       = (float*)d_out;
    float* out_loss  = out;                                   // [B]
    float* out_align = out + B_;                              // [B, T, L]
    float* out_lp    = out_align + (size_t)B_ * T_ * L_;      // [B, L, T]

    cudaFuncSetAttribute(k2_dp, cudaFuncAttributeMaxDynamicSharedMemorySize,
                         SMB_TOT);

    kz_zero<<<2048, 256>>>((float4*)out_align, (B_ * T_ * L_) / 4);
    k0_coef<<<(B_ * L_) / 128, 128>>>(mu_logvar);
    dim3 g1(T_ / 64, L_ / 128, B_);
    k1_lp<<<g1, 256>>>(z, out_lp);
    k2_dp<<<B_, 256, SMB_TOT>>>(out_lp, tlen, mlen, out_loss, out_align);
}

// round 12
// speedup vs baseline: 1.3523x; 1.3523x over previous
#include <cuda_runtime.h>
#include <cstdint>

#define B_   32
#define L_   256
#define T_   1600
#define C_   40
#define PADM 1.0e12f

// ---------------- scratch (__device__ globals; no allocation allowed) ----------------
__device__ __align__(16) float g_coefA[B_ * C_ * 2 * L_];   // invvar, duplicated pairs
__device__ __align__(16) float g_coefB[B_ * C_ * 2 * L_];   // -2*mu*invvar, duplicated pairs
__device__ __align__(16) float g_t3 [B_ * L_];
__device__ __align__(16) float g_mlv[B_ * L_];

// ---------------- packed f32x2 helpers (sm_103a) ----------------
__device__ __forceinline__ unsigned long long pack2(float lo, float hi) {
    unsigned long long r;
    asm("mov.b64 %0, {%1,%2};" : "=l"(r) : "f"(lo), "f"(hi));
    return r;
}
#define FFMA2_ACC(d, a, b) \
    asm("fma.rn.f32x2 %0, %1, %2, %0;" : "+l"(d) : "l"(a), "l"(b))
#define FFMA2(d, a, b, c) \
    asm("fma.rn.f32x2 %0, %1, %2, %3;" : "=l"(d) : "l"(a), "l"(b), "l"(c))
#define ADD2(d, a, b) \
    asm("add.rn.f32x2 %0, %1, %2;" : "=l"(d) : "l"(a), "l"(b))

// volatile 128-bit shared ld/st (single-instruction mailbox access)
__device__ __forceinline__ uint4 ldsv4v(unsigned a) {
    uint4 r;
    asm volatile("ld.volatile.shared.v4.b32 {%0,%1,%2,%3},[%4];"
                 : "=r"(r.x), "=r"(r.y), "=r"(r.z), "=r"(r.w) : "r"(a));
    return r;
}
__device__ __forceinline__ void stsv4v(unsigned a, uint4 v) {
    asm volatile("st.volatile.shared.v4.b32 [%0],{%1,%2,%3,%4};"
                 :: "r"(a), "r"(v.x), "r"(v.y), "r"(v.z), "r"(v.w));
}

// ---------------- K0: per-(b,l) coefficients ----------------
__global__ void k0_coef(const float* __restrict__ mu_logvar) {
    int idx = blockIdx.x * 128 + threadIdx.x;          // 0 .. B*L-1
    int b = idx >> 8;
    int l = idx & (L_ - 1);
    const float* row = mu_logvar + (size_t)idx * (2 * C_);
    float* A  = g_coefA + (size_t)b * C_ * 2 * L_ + 2 * l;
    float* Bc = g_coefB + (size_t)b * C_ * 2 * L_ + 2 * l;
    float t3 = 0.f, slv = 0.f;
    for (int c = 0; c < C_; c++) {
        float mu = row[c];
        float lv = row[C_ + c];
        float iv = expf(-lv);
        float miv = mu * iv;
        float m2 = -2.0f * miv;
        A [c * 2 * L_]     = iv;
        A [c * 2 * L_ + 1] = iv;
        Bc[c * 2 * L_]     = m2;
        Bc[c * 2 * L_ + 1] = m2;
        t3 = fmaf(mu, miv, t3);
        slv += lv;
    }
    g_t3 [idx] = t3;
    g_mlv[idx] = slv * (1.0f / C_);
}

// ---------------- K1: lp[b][l][t], single-accumulator FFMA2 GEMM ----------------
// block = all 256 l x 64 t, 256 threads, thread tile 4 l x 16 t
__global__ __launch_bounds__(256) void k1_lp(const float* __restrict__ z,
                                             float* __restrict__ lp_out) {
    __shared__ __align__(16) float zs[C_][64];
    int b  = blockIdx.y;
    int t0 = blockIdx.x * 64;
    int tid = threadIdx.x;

    const float* zb = z + (size_t)b * C_ * T_ + t0;
    for (int i = tid; i < C_ * 64; i += 256) {
        int c = i >> 6, j = i & 63;
        zs[c][j] = zb[(size_t)c * T_ + j];
    }
    __syncthreads();

    int lg = tid >> 2;            // 0..63 -> rows 4lg..4lg+3
    int tg = tid & 3;             // 0..3  -> t cols tg*16..tg*16+15
    int lbase = lg * 4;

    unsigned long long acc[4][8];
#pragma unroll
    for (int r = 0; r < 4; r++)
#pragma unroll
        for (int j = 0; j < 8; j++) acc[r][j] = 0ull;

    const float* cA = g_coefA + (size_t)b * C_ * 2 * L_ + 2 * lbase;
    const float* cB = g_coefB + (size_t)b * C_ * 2 * L_ + 2 * lbase;

#pragma unroll 2
    for (int c = 0; c < C_; c++) {
        ulonglong2 aL = *(const ulonglong2*)(cA + (size_t)c * 2 * L_);
        ulonglong2 aH = *(const ulonglong2*)(cA + (size_t)c * 2 * L_ + 4);
        ulonglong2 bL = *(const ulonglong2*)(cB + (size_t)c * 2 * L_);
        ulonglong2 bH = *(const ulonglong2*)(cB + (size_t)c * 2 * L_ + 4);
        unsigned long long ar[4] = {aL.x, aL.y, aH.x, aH.y};
        unsigned long long br[4] = {bL.x, bL.y, bH.x, bH.y};
        unsigned long long zp[8];
        {
            const ulonglong2* zrow = (const ulonglong2*)&zs[c][tg * 16];
            ulonglong2 w0 = zrow[0], w1 = zrow[1], w2 = zrow[2], w3 = zrow[3];
            zp[0] = w0.x; zp[1] = w0.y; zp[2] = w1.x; zp[3] = w1.y;
            zp[4] = w2.x; zp[5] = w2.y; zp[6] = w3.x; zp[7] = w3.y;
        }
#pragma unroll
        for (int r = 0; r < 4; r++) {
#pragma unroll
            for (int j = 0; j < 8; j++) {
                unsigned long long tmp;
                FFMA2(tmp, ar[r], zp[j], br[r]);     // iv*z + (-2*miv)
                FFMA2_ACC(acc[r][j], tmp, zp[j]);    // acc += (iv*z - 2miv)*z
            }
        }
    }

    float4 t34 = *(const float4*)(g_t3  + b * L_ + lbase);
    float4 mv4 = *(const float4*)(g_mlv + b * L_ + lbase);
    float t3a[4] = {t34.x, t34.y, t34.z, t34.w};
    float mva[4] = {mv4.x, mv4.y, mv4.z, mv4.w};
    unsigned long long c1 = pack2(-0.0125f, -0.0125f);   // -0.5/C
#pragma unroll
    for (int r = 0; r < 4; r++) {
        unsigned long long tp = pack2(t3a[r], t3a[r]);
        unsigned long long dp = pack2(-0.5f * mva[r], -0.5f * mva[r]);
        unsigned long long o[8];
#pragma unroll
        for (int j = 0; j < 8; j++) {
            unsigned long long mse;
            ADD2(mse, acc[r][j], tp);                // + t3
            FFMA2(o[j], mse, c1, dp);                // *(-1/80) + (-0.5*mlv)
        }
        float* orow = lp_out + ((size_t)b * L_ + lbase + r) * T_ + t0 + tg * 16;
        ((ulonglong2*)orow)[0] = make_ulonglong2(o[0], o[1]);
        ((ulonglong2*)orow)[1] = make_ulonglong2(o[2], o[3]);
        ((ulonglong2*)orow)[2] = make_ulonglong2(o[4], o[5]);
        ((ulonglong2*)orow)[3] = make_ulonglong2(o[6], o[7]);
    }
}

// ---------------- K2: forward DP + Viterbi (R6 tagged-ring version, verbatim) ------
// + prologue: zero this batch's alignment slab (replaces kz_zero kernel)
// smem layout (dynamic):
//   [0, 51200)        D: decision ballot words [T_][8]
//   [51200, 55296)    mailbox: 8 warps x 32 slots x 16B {tag, alpha, beta, pad}
//   [55296, 61696)    path[T_]
//   [61696, 61700)    shv (alpha at (tl-1, ml-1))
#define SM2_MB   51200
#define SM2_PATH 55296
#define SM2_SHV  61696
#define SM2_TOT  61712

__global__ __launch_bounds__(256, 1) void k2_dp(const float* __restrict__ lp,
                                                const int* __restrict__ tlen,
                                                const int* __restrict__ mlen,
                                                float* __restrict__ out_loss,
                                                float* __restrict__ out_align) {
    extern __shared__ unsigned char smraw[];
    unsigned* D = (unsigned*)smraw;
    int* path   = (int*)(smraw + SM2_PATH);
    float* shv  = (float*)(smraw + SM2_SHV);
    unsigned smbase = (unsigned)__cvta_generic_to_shared(smraw);
    unsigned mbbase = smbase + SM2_MB;

    int b = blockIdx.x;
    int l = threadIdx.x;
    int w = l >> 5, lane = l & 31;
    int ml = mlen[b], tl = tlen[b];

    // prologue: zero this batch's alignment output slab (fire-and-forget)
    {
        float4* ap = (float4*)(out_align + (size_t)b * T_ * L_);
        float4 z4 = make_float4(0.f, 0.f, 0.f, 0.f);
        for (int i = l; i < (T_ * L_) / 4; i += 256) ap[i] = z4;
    }

    const float* p = lp + ((size_t)b * L_ + l) * T_;

    unsigned mb_self = mbbase + (unsigned)w * 512u;
    unsigned mb_src  = mbbase + (unsigned)((w + 7) & 7) * 512u;  // warp w-1 (warp0 -> warp7)

    float4 vcur = *(const float4*)p;           // lp[t=0..3]
    float a  = (l == 0) ? vcur.x : -PADM;      // alpha(t=0)
    float bt = a;                              // beta(t=0)

    // publish init slot (lane31 values at t=0 are all -PADM)
    if (lane == 31)
        stsv4v(mb_self, make_uint4(0u, __float_as_uint(-PADM), __float_as_uint(-PADM), 0u));
    __syncthreads();   // make init slots + tag space visible (only barrier before loop)

    float4 vnext = *(const float4*)(p + 4);

    for (int k = 0; k < T_ / 4; k++) {
        float4 vpref = vcur;
        if (k + 2 < T_ / 4) vpref = *(const float4*)(p + 4 * (k + 2));
        float lt[4] = {vcur.x, vcur.y, vcur.z, vcur.w};
#pragma unroll
        for (int j = 0; j < 4; j++) {
            int t = 4 * k + j;
            if (t == 0) continue;
            // poll producer boundary slot for step t-1
            unsigned tag = (unsigned)(t - 1);
            unsigned saddr = mb_src + (tag & 31u) * 16u;
            uint4 s = ldsv4v(saddr);
            while (s.x != tag) s = ldsv4v(saddr);
            float mba = __uint_as_float(s.y);
            float mbb = __uint_as_float(s.z);
            // neighbor values at t-1
            float sa = __shfl_up_sync(0xffffffffu, a, 1);
            float sb = __shfl_up_sync(0xffffffffu, bt, 1);
            float am, bm, bw;
            if (lane == 0) {
                bw = mbb;                         // ballot wrap: beta[l-1 mod 256]
                if (w == 0) { am = -PADM; bm = -PADM; }
                else        { am = mba;   bm = mbb; }
            } else { am = sa; bm = sb; bw = sb; }
            // decision bits for column t-1 (beta values at t-1)
            unsigned bal = __ballot_sync(0xffffffffu, bw > bt);
            if (lane == 0) D[(t - 1) * 8 + w] = bal;
            // recurrences
            float lpv = lt[j];
            float d  = a - am;
            float m  = fmaxf(a, am);
            float an = m + __logf(1.0f + __expf(-fabsf(d))) + (lpv + 1e-7f);
            float bn = fmaxf(bt, bm) + lpv;
            if (t == ml - 1 && l == tl - 1) *shv = an;
            if (lane == 31)
                stsv4v(mb_self + ((unsigned)t & 31u) * 16u,
                       make_uint4((unsigned)t, __float_as_uint(an), __float_as_uint(bn), 0u));
            a = an; bt = bn;
        }
        vcur = vnext; vnext = vpref;
    }
    // bits for the last column (t = T-1)
    {
        unsigned tag = (unsigned)(T_ - 1);
        unsigned saddr = mb_src + (tag & 31u) * 16u;
        uint4 s = ldsv4v(saddr);
        while (s.x != tag) s = ldsv4v(saddr);
        float sb = __shfl_up_sync(0xffffffffu, bt, 1);
        float bw = (lane == 0) ? __uint_as_float(s.z) : sb;
        unsigned bal = __ballot_sync(0xffffffffu, bw > bt);
        if (lane == 0) D[(T_ - 1) * 8 + w] = bal;
    }
    __syncthreads();

    // serial backtrack (exact emulation of reference relu/mod arithmetic)
    if (l == 0) {
        out_loss[b] = -(*shv) / (float)ml;
        int rows = tl - 1, cols = ml - 1;
        path[0] = rows;
        for (int k = 1; k < ml; k++) {
            int col = ((cols - 1) % T_ + T_) % T_;
            int br_ = rows & (L_ - 1);           // python mod for rows >= -1
            unsigned wv = D[col * 8 + (br_ >> 5)];
            int is_go = (wv >> (br_ & 31)) & 1;
            int tmp = rows - is_go + 1;
            rows = (tmp > 0 ? tmp : 0) - 1;
            cols = (cols > 0 ? cols : 0) - 1;
            path[k] = rows;
        }
    }
    __syncthreads();

    // write one-hot ones: final[t] = onehot(path[ml-1-t]) for t < ml
    size_t abase = (size_t)b * T_ * L_;
    for (int t = l; t < ml; t += 256) {
        int r = path[ml - 1 - t];
        if (r >= 0) out_align[abase + (size_t)t * L_ + r] = 1.0f;
    }
}

// ---------------- launch ----------------
extern "C" void kernel_launch(void* const* d_in, const int* in_sizes, int n_in,
                              void* d_out, int out_size) {
    const float* mu_logvar = (const float*)d_in[0];   // [B, L, 2C]
    const float* z         = (const float*)d_in[1];   // [B, C, T]
    const int*   tlen      = (const int*)d_in[2];     // [B]
    const int*   mlen      = (const int*)d_in[3];     // [B]

    float* out       = (float*)d_out;
    float* out_loss  = out;                                   // [B]
    float* out_align = out + B_;                              // [B, T, L]
    float* out_lp    = out_align + (size_t)B_ * T_ * L_;      // [B, L, T]

    cudaFuncSetAttribute(k2_dp, cudaFuncAttributeMaxDynamicSharedMemorySize,
                         SM2_TOT);

    k0_coef<<<(B_ * L_) / 128, 128>>>(mu_logvar);
    dim3 g1(T_ / 64, B_);
    k1_lp<<<g1, 256>>>(z, out_lp);
    k2_dp<<<B_, 256, SM2_TOT>>>(out_lp, tlen, mlen, out_loss, out_align);
}

// round 13
// speedup vs baseline: 1.7195x; 1.2716x over previous
#include <cuda_runtime.h>
#include <cstdint>

#define B_   32
#define L_   256
#define T_   1600
#define C_   40
#define PADM 1.0e12f
#define NCH  25          // 25 chunks of 64 t-columns

// ---------------- scratch (__device__ globals; no allocation allowed) ----------------
__device__ __align__(16) float g_coefA[B_ * C_ * 2 * L_];   // invvar, duplicated pairs
__device__ __align__(16) float g_coefB[B_ * C_ * 2 * L_];   // -2*mu*invvar, duplicated pairs
__device__ __align__(16) float g_t3 [B_ * L_];
__device__ __align__(16) float g_mlv[B_ * L_];
__device__ int g_flag[B_ * NCH];    // lp chunk ready flags
__device__ int g_zc;                // alignment-zeroing completion counter

// ---------------- packed f32x2 helpers (sm_103a) ----------------
__device__ __forceinline__ unsigned long long pack2(float lo, float hi) {
    unsigned long long r;
    asm("mov.b64 %0, {%1,%2};" : "=l"(r) : "f"(lo), "f"(hi));
    return r;
}
#define FFMA2_ACC(d, a, b) \
    asm("fma.rn.f32x2 %0, %1, %2, %0;" : "+l"(d) : "l"(a), "l"(b))
#define FFMA2(d, a, b, c) \
    asm("fma.rn.f32x2 %0, %1, %2, %3;" : "=l"(d) : "l"(a), "l"(b), "l"(c))
#define ADD2(d, a, b) \
    asm("add.rn.f32x2 %0, %1, %2;" : "=l"(d) : "l"(a), "l"(b))

// volatile 128-bit shared ld/st (single-instruction mailbox access)
__device__ __forceinline__ uint4 ldsv4v(unsigned a) {
    uint4 r;
    asm volatile("ld.volatile.shared.v4.b32 {%0,%1,%2,%3},[%4];"
                 : "=r"(r.x), "=r"(r.y), "=r"(r.z), "=r"(r.w) : "r"(a));
    return r;
}
__device__ __forceinline__ void stsv4v(unsigned a, uint4 v) {
    asm volatile("st.volatile.shared.v4.b32 [%0],{%1,%2,%3,%4};"
                 :: "r"(a), "r"(v.x), "r"(v.y), "r"(v.z), "r"(v.w));
}
__device__ __forceinline__ void waitflag(int idx) {
    volatile int* f = g_flag;
    while (f[idx] == 0) {}
    __threadfence();
}

// ---------------- K0: per-(b,l) coefficients + flag reset ----------------
__global__ void k0_coef(const float* __restrict__ mu_logvar) {
    int idx = blockIdx.x * 128 + threadIdx.x;          // 0 .. B*L-1
    if (idx < B_ * NCH) g_flag[idx] = 0;
    if (idx == B_ * NCH) g_zc = 0;
    int b = idx >> 8;
    int l = idx & (L_ - 1);
    const float* row = mu_logvar + (size_t)idx * (2 * C_);
    float* A  = g_coefA + (size_t)b * C_ * 2 * L_ + 2 * l;
    float* Bc = g_coefB + (size_t)b * C_ * 2 * L_ + 2 * l;
    float t3 = 0.f, slv = 0.f;
    for (int c = 0; c < C_; c++) {
        float mu = row[c];
        float lv = row[C_ + c];
        float iv = expf(-lv);
        float miv = mu * iv;
        float m2 = -2.0f * miv;
        A [c * 2 * L_]     = iv;
        A [c * 2 * L_ + 1] = iv;
        Bc[c * 2 * L_]     = m2;
        Bc[c * 2 * L_ + 1] = m2;
        t3 = fmaf(mu, miv, t3);
        slv += lv;
    }
    g_t3 [idx] = t3;
    g_mlv[idx] = slv * (1.0f / C_);
}

// ---------------- fused kernel: blocks 0..31 = DP, blocks 32..831 = lp GEMM -------
// DP smem layout (dynamic):
//   [0, 51200)        D: decision ballot words [T_][8]
//   [51200, 55296)    mailbox: 8 warps x 32 slots x 16B {tag, alpha, beta, pad}
//   [55296, 61696)    path[T_]
//   [61696, 61700)    shv (alpha at (tl-1, ml-1))
// GEMM role reuses the same buffer for zs[40][64] (10240 B).
#define SM2_MB   51200
#define SM2_PATH 55296
#define SM2_SHV  61696
#define SM2_TOT  61712

// ---- GEMM role: lp for (batch b, chunk c) + zero slab share + publish flag ----
__device__ void k1_role(int b, int c, const float* __restrict__ z,
                        float* __restrict__ lp_out, float* __restrict__ out_align,
                        unsigned char* smraw) {
    float* zs = (float*)smraw;                // [C_][64]
    int t0 = c * 64;
    int tid = threadIdx.x;

    // zero this (b, c) share of the alignment output (4096 float4)
    {
        float4* ap = (float4*)(out_align + (size_t)b * T_ * L_) + c * 4096;
        float4 z4 = make_float4(0.f, 0.f, 0.f, 0.f);
#pragma unroll
        for (int q = 0; q < 16; q++) ap[tid + q * 256] = z4;
    }

    const float* zb = z + (size_t)b * C_ * T_ + t0;
    for (int i = tid; i < C_ * 64; i += 256) {
        int cc = i >> 6, j = i & 63;
        zs[cc * 64 + j] = zb[(size_t)cc * T_ + j];
    }
    __syncthreads();

    int lg = tid >> 2;            // 0..63 -> rows 4lg..4lg+3
    int tg = tid & 3;             // 0..3  -> t cols tg*16..tg*16+15
    int lbase = lg * 4;

    unsigned long long acc[4][8];
#pragma unroll
    for (int r = 0; r < 4; r++)
#pragma unroll
        for (int j = 0; j < 8; j++) acc[r][j] = 0ull;

    const float* cA = g_coefA + (size_t)b * C_ * 2 * L_ + 2 * lbase;
    const float* cB = g_coefB + (size_t)b * C_ * 2 * L_ + 2 * lbase;

#pragma unroll 2
    for (int cc = 0; cc < C_; cc++) {
        ulonglong2 aL = *(const ulonglong2*)(cA + (size_t)cc * 2 * L_);
        ulonglong2 aH = *(const ulonglong2*)(cA + (size_t)cc * 2 * L_ + 4);
        ulonglong2 bL = *(const ulonglong2*)(cB + (size_t)cc * 2 * L_);
        ulonglong2 bH = *(const ulonglong2*)(cB + (size_t)cc * 2 * L_ + 4);
        unsigned long long ar[4] = {aL.x, aL.y, aH.x, aH.y};
        unsigned long long br[4] = {bL.x, bL.y, bH.x, bH.y};
        unsigned long long zp[8];
        {
            const ulonglong2* zrow = (const ulonglong2*)(zs + cc * 64 + tg * 16);
            ulonglong2 w0 = zrow[0], w1 = zrow[1], w2 = zrow[2], w3 = zrow[3];
            zp[0] = w0.x; zp[1] = w0.y; zp[2] = w1.x; zp[3] = w1.y;
            zp[4] = w2.x; zp[5] = w2.y; zp[6] = w3.x; zp[7] = w3.y;
        }
#pragma unroll
        for (int r = 0; r < 4; r++) {
#pragma unroll
            for (int j = 0; j < 8; j++) {
                unsigned long long tmp;
                FFMA2(tmp, ar[r], zp[j], br[r]);     // iv*z + (-2*miv)
                FFMA2_ACC(acc[r][j], tmp, zp[j]);    // acc += (iv*z - 2miv)*z
            }
        }
    }

    float4 t34 = *(const float4*)(g_t3  + b * L_ + lbase);
    float4 mv4 = *(const float4*)(g_mlv + b * L_ + lbase);
    float t3a[4] = {t34.x, t34.y, t34.z, t34.w};
    float mva[4] = {mv4.x, mv4.y, mv4.z, mv4.w};
    unsigned long long c1 = pack2(-0.0125f, -0.0125f);   // -0.5/C
#pragma unroll
    for (int r = 0; r < 4; r++) {
        unsigned long long tp = pack2(t3a[r], t3a[r]);
        unsigned long long dp = pack2(-0.5f * mva[r], -0.5f * mva[r]);
        unsigned long long o[8];
#pragma unroll
        for (int j = 0; j < 8; j++) {
            unsigned long long mse;
            ADD2(mse, acc[r][j], tp);                // + t3
            FFMA2(o[j], mse, c1, dp);                // *(-1/80) + (-0.5*mlv)
        }
        float* orow = lp_out + ((size_t)b * L_ + lbase + r) * T_ + t0 + tg * 16;
        ((ulonglong2*)orow)[0] = make_ulonglong2(o[0], o[1]);
        ((ulonglong2*)orow)[1] = make_ulonglong2(o[2], o[3]);
        ((ulonglong2*)orow)[2] = make_ulonglong2(o[4], o[5]);
        ((ulonglong2*)orow)[3] = make_ulonglong2(o[6], o[7]);
    }

    __threadfence();
    if (tid == 0) {
        atomicExch(&g_flag[b * NCH + c], 1);
        atomicAdd(&g_zc, 1);
    }
}

// ---- DP role: R6 tagged-ring forward+viterbi, chunk-gated on g_flag ----
__device__ void k2_role(int b, const float* __restrict__ lp,
                        const int* __restrict__ tlen, const int* __restrict__ mlen,
                        float* __restrict__ out_loss, float* __restrict__ out_align,
                        unsigned char* smraw) {
    unsigned* D = (unsigned*)smraw;
    int* path   = (int*)(smraw + SM2_PATH);
    float* shv  = (float*)(smraw + SM2_SHV);
    unsigned smbase = (unsigned)__cvta_generic_to_shared(smraw);
    unsigned mbbase = smbase + SM2_MB;

    int l = threadIdx.x;
    int w = l >> 5, lane = l & 31;
    int ml = mlen[b], tl = tlen[b];

    const float* p = lp + ((size_t)b * L_ + l) * T_;

    unsigned mb_self = mbbase + (unsigned)w * 512u;
    unsigned mb_src  = mbbase + (unsigned)((w + 7) & 7) * 512u;  // warp w-1 (warp0 -> warp7)

    waitflag(b * NCH + 0);                     // chunk 0 ready
    float4 vcur = *(const float4*)p;           // lp[t=0..3]
    float a  = (l == 0) ? vcur.x : -PADM;      // alpha(t=0)
    float bt = a;                              // beta(t=0)

    // publish init slot (lane31 values at t=0 are all -PADM)
    if (lane == 31)
        stsv4v(mb_self, make_uint4(0u, __float_as_uint(-PADM), __float_as_uint(-PADM), 0u));
    __syncthreads();   // make init slots + tag space visible (only barrier before loop)

    waitflag(b * NCH + 1);                     // covers prefetch into chunk 1
    float4 vnext = *(const float4*)(p + 4);

    for (int c = 0; c < NCH; c++) {
        if (c >= 1) {
            int nf = c + 1 < NCH ? c + 1 : NCH - 1;
            waitflag(b * NCH + nf);            // covers chunk c prefetch window
        }
#pragma unroll 1
        for (int kk = 0; kk < 16; kk++) {
            int k = c * 16 + kk;
            float4 vpref = vcur;
            if (k + 2 < T_ / 4) vpref = *(const float4*)(p + 4 * (k + 2));
            float lt[4] = {vcur.x, vcur.y, vcur.z, vcur.w};
#pragma unroll
            for (int j = 0; j < 4; j++) {
                int t = 4 * k + j;
                if (t == 0) continue;
                // poll producer boundary slot for step t-1
                unsigned tag = (unsigned)(t - 1);
                unsigned saddr = mb_src + (tag & 31u) * 16u;
                uint4 s = ldsv4v(saddr);
                while (s.x != tag) s = ldsv4v(saddr);
                float mba = __uint_as_float(s.y);
                float mbb = __uint_as_float(s.z);
                // neighbor values at t-1
                float sa = __shfl_up_sync(0xffffffffu, a, 1);
                float sb = __shfl_up_sync(0xffffffffu, bt, 1);
                float am, bm, bw;
                if (lane == 0) {
                    bw = mbb;                         // ballot wrap: beta[l-1 mod 256]
                    if (w == 0) { am = -PADM; bm = -PADM; }
                    else        { am = mba;   bm = mbb; }
                } else { am = sa; bm = sb; bw = sb; }
                // decision bits for column t-1 (beta values at t-1)
                unsigned bal = __ballot_sync(0xffffffffu, bw > bt);
                if (lane == 0) D[(t - 1) * 8 + w] = bal;
                // recurrences
                float lpv = lt[j];
                float d  = a - am;
                float m  = fmaxf(a, am);
                float an = m + __logf(1.0f + __expf(-fabsf(d))) + (lpv + 1e-7f);
                float bn = fmaxf(bt, bm) + lpv;
                if (t == ml - 1 && l == tl - 1) *shv = an;
                if (lane == 31)
                    stsv4v(mb_self + ((unsigned)t & 31u) * 16u,
                           make_uint4((unsigned)t, __float_as_uint(an), __float_as_uint(bn), 0u));
                a = an; bt = bn;
            }
            vcur = vnext; vnext = vpref;
        }
    }
    // bits for the last column (t = T-1)
    {
        unsigned tag = (unsigned)(T_ - 1);
        unsigned saddr = mb_src + (tag & 31u) * 16u;
        uint4 s = ldsv4v(saddr);
        while (s.x != tag) s = ldsv4v(saddr);
        float sb = __shfl_up_sync(0xffffffffu, bt, 1);
        float bw = (lane == 0) ? __uint_as_float(s.z) : sb;
        unsigned bal = __ballot_sync(0xffffffffu, bw > bt);
        if (lane == 0) D[(T_ - 1) * 8 + w] = bal;
    }
    __syncthreads();

    // serial backtrack (exact emulation of reference relu/mod arithmetic)
    if (l == 0) {
        out_loss[b] = -(*shv) / (float)ml;
        int rows = tl - 1, cols = ml - 1;
        path[0] = rows;
        for (int k = 1; k < ml; k++) {
            int col = ((cols - 1) % T_ + T_) % T_;
            int br_ = rows & (L_ - 1);           // python mod for rows >= -1
            unsigned wv = D[col * 8 + (br_ >> 5)];
            int is_go = (wv >> (br_ & 31)) & 1;
            int tmp = rows - is_go + 1;
            rows = (tmp > 0 ? tmp : 0) - 1;
            cols = (cols > 0 ? cols : 0) - 1;
            path[k] = rows;
        }
        // all alignment-zeroing blocks must be done before one-hot writes
        volatile int* zc = &g_zc;
        while (*zc != B_ * NCH) {}
        __threadfence();
    }
    __syncthreads();

    // write one-hot ones: final[t] = onehot(path[ml-1-t]) for t < ml
    size_t abase = (size_t)b * T_ * L_;
    for (int t = l; t < ml; t += 256) {
        int r = path[ml - 1 - t];
        if (r >= 0) out_align[abase + (size_t)t * L_ + r] = 1.0f;
    }
}

__global__ __launch_bounds__(256, 1) void k12_fused(const float* __restrict__ z,
                                                    float* __restrict__ lp_out,
                                                    const int* __restrict__ tlen,
                                                    const int* __restrict__ mlen,
                                                    float* __restrict__ out_loss,
                                                    float* __restrict__ out_align) {
    extern __shared__ unsigned char smraw[];
    if (blockIdx.x < B_) {
        k2_role(blockIdx.x, lp_out, tlen, mlen, out_loss, out_align, smraw);
    } else {
        int i = blockIdx.x - B_;
        int b = i & (B_ - 1);      // batch fastest -> every batch's chunk 0 in wave 1
        int c = i >> 5;
        k1_role(b, c, z, lp_out, out_align, smraw);
    }
}

// ---------------- launch ----------------
extern "C" void kernel_launch(void* const* d_in, const int* in_sizes, int n_in,
                              void* d_out, int out_size) {
    const float* mu_logvar = (const float*)d_in[0];   // [B, L, 2C]
    const float* z         = (const float*)d_in[1];   // [B, C, T]
    const int*   tlen      = (const int*)d_in[2];     // [B]
    const int*   mlen      = (const int*)d_in[3];     // [B]

    float* out       = (float*)d_out;
    float* out_loss  = out;                                   // [B]
    float* out_align = out + B_;                              // [B, T, L]
    float* out_lp    = out_align + (size_t)B_ * T_ * L_;      // [B, L, T]

    cudaFuncSetAttribute(k12_fused, cudaFuncAttributeMaxDynamicSharedMemorySize,
                         SM2_TOT);

    k0_coef<<<(B_ * L_) / 128, 128>>>(mu_logvar);
    k12_fused<<<B_ + B_ * NCH, 256, SM2_TOT>>>(z, out_lp, tlen, mlen,
                                               out_loss, out_align);
}

// round 14
// speedup vs baseline: 2.3036x; 1.3397x over previous
#include <cuda_runtime.h>
#include <cstdint>

#define B_   32
#define L_   256
#define T_   1600
#define C_   40
#define PADM 1.0e12f
#define NCH  25          // 25 chunks of 64 t-columns

// ---------------- scratch (__device__ globals; no allocation allowed) ----------------
__device__ __align__(16) float g_coefA[B_ * C_ * 2 * L_];   // invvar, duplicated pairs
__device__ __align__(16) float g_coefB[B_ * C_ * 2 * L_];   // -2*mu*invvar, duplicated pairs
__device__ __align__(16) float g_t3 [B_ * L_];
__device__ __align__(16) float g_mlv[B_ * L_];
__device__ int g_flag[B_ * NCH];    // lp chunk ready flags
__device__ int g_zc;                // alignment-zeroing completion counter

// ---------------- packed f32x2 helpers (sm_103a) ----------------
__device__ __forceinline__ unsigned long long pack2(float lo, float hi) {
    unsigned long long r;
    asm("mov.b64 %0, {%1,%2};" : "=l"(r) : "f"(lo), "f"(hi));
    return r;
}
#define FFMA2_ACC(d, a, b) \
    asm("fma.rn.f32x2 %0, %1, %2, %0;" : "+l"(d) : "l"(a), "l"(b))
#define FFMA2(d, a, b, c) \
    asm("fma.rn.f32x2 %0, %1, %2, %3;" : "=l"(d) : "l"(a), "l"(b), "l"(c))
#define ADD2(d, a, b) \
    asm("add.rn.f32x2 %0, %1, %2;" : "=l"(d) : "l"(a), "l"(b))

// volatile 128-bit shared ld/st
__device__ __forceinline__ uint4 ldsv4v(unsigned a) {
    uint4 r;
    asm volatile("ld.volatile.shared.v4.b32 {%0,%1,%2,%3},[%4];"
                 : "=r"(r.x), "=r"(r.y), "=r"(r.z), "=r"(r.w) : "r"(a));
    return r;
}
__device__ __forceinline__ void stsv4v(unsigned a, uint4 v) {
    asm volatile("st.volatile.shared.v4.b32 [%0],{%1,%2,%3,%4};"
                 :: "r"(a), "r"(v.x), "r"(v.y), "r"(v.z), "r"(v.w));
}
__device__ __forceinline__ void waitflag(int idx) {
    volatile int* f = g_flag;
    while (f[idx] == 0) {}
    __threadfence();
}

// ---------------- K0: per-(b,l) coefficients + flag reset ----------------
__global__ void k0_coef(const float* __restrict__ mu_logvar) {
    int idx = blockIdx.x * 128 + threadIdx.x;          // 0 .. B*L-1
    if (idx < B_ * NCH) g_flag[idx] = 0;
    if (idx == B_ * NCH) g_zc = 0;
    int b = idx >> 8;
    int l = idx & (L_ - 1);
    const float* row = mu_logvar + (size_t)idx * (2 * C_);
    float* A  = g_coefA + (size_t)b * C_ * 2 * L_ + 2 * l;
    float* Bc = g_coefB + (size_t)b * C_ * 2 * L_ + 2 * l;
    float t3 = 0.f, slv = 0.f;
    for (int c = 0; c < C_; c++) {
        float mu = row[c];
        float lv = row[C_ + c];
        float iv = expf(-lv);
        float miv = mu * iv;
        float m2 = -2.0f * miv;
        A [c * 2 * L_]     = iv;
        A [c * 2 * L_ + 1] = iv;
        Bc[c * 2 * L_]     = m2;
        Bc[c * 2 * L_ + 1] = m2;
        t3 = fmaf(mu, miv, t3);
        slv += lv;
    }
    g_t3 [idx] = t3;
    g_mlv[idx] = slv * (1.0f / C_);
}

// ---------------- smem layout (fused kernel) ----------------
//   [0, 51200)          D: decision ballot words [T_][8]
//   [51200, 204800)     mailbox: 8 warps x 400 groups x 48B
//                       slot: w0{tag=k+1, a0, b0, pad} w1{a1,b1,a2,b2} w2{a3,b3,-,-}
//   [204800, 211200)    b0h[T_]  beta[l=0] history
//   [211200, 217600)    path[T_]
//   [217600, 217604)    shv
// GEMM role reuses the front of the buffer for zs[40][64] (10240 B).
#define SMB_MB   51200
#define SMB_B0H  204800
#define SMB_PATH 211200
#define SMB_SHV  217600
#define SMB_TOT  217616
#define WSTRIDE  19200u   // 400 * 48

// ---- GEMM role: lp for (batch b, chunk c) + zero slab share + publish flag ----
__device__ void k1_role(int b, int c, const float* __restrict__ z,
                        float* __restrict__ lp_out, float* __restrict__ out_align,
                        unsigned char* smraw) {
    float* zs = (float*)smraw;                // [C_][64]
    int t0 = c * 64;
    int tid = threadIdx.x;

    // zero this (b, c) share of the alignment output (4096 float4)
    {
        float4* ap = (float4*)(out_align + (size_t)b * T_ * L_) + c * 4096;
        float4 z4 = make_float4(0.f, 0.f, 0.f, 0.f);
#pragma unroll
        for (int q = 0; q < 16; q++) ap[tid + q * 256] = z4;
    }

    const float* zb = z + (size_t)b * C_ * T_ + t0;
    for (int i = tid; i < C_ * 64; i += 256) {
        int cc = i >> 6, j = i & 63;
        zs[cc * 64 + j] = zb[(size_t)cc * T_ + j];
    }
    __syncthreads();

    int lg = tid >> 2;
    int tg = tid & 3;
    int lbase = lg * 4;

    unsigned long long acc[4][8];
#pragma unroll
    for (int r = 0; r < 4; r++)
#pragma unroll
        for (int j = 0; j < 8; j++) acc[r][j] = 0ull;

    const float* cA = g_coefA + (size_t)b * C_ * 2 * L_ + 2 * lbase;
    const float* cB = g_coefB + (size_t)b * C_ * 2 * L_ + 2 * lbase;

#pragma unroll 2
    for (int cc = 0; cc < C_; cc++) {
        ulonglong2 aL = *(const ulonglong2*)(cA + (size_t)cc * 2 * L_);
        ulonglong2 aH = *(const ulonglong2*)(cA + (size_t)cc * 2 * L_ + 4);
        ulonglong2 bL = *(const ulonglong2*)(cB + (size_t)cc * 2 * L_);
        ulonglong2 bH = *(const ulonglong2*)(cB + (size_t)cc * 2 * L_ + 4);
        unsigned long long ar[4] = {aL.x, aL.y, aH.x, aH.y};
        unsigned long long br[4] = {bL.x, bL.y, bH.x, bH.y};
        unsigned long long zp[8];
        {
            const ulonglong2* zrow = (const ulonglong2*)(zs + cc * 64 + tg * 16);
            ulonglong2 w0 = zrow[0], w1 = zrow[1], w2 = zrow[2], w3 = zrow[3];
            zp[0] = w0.x; zp[1] = w0.y; zp[2] = w1.x; zp[3] = w1.y;
            zp[4] = w2.x; zp[5] = w2.y; zp[6] = w3.x; zp[7] = w3.y;
        }
#pragma unroll
        for (int r = 0; r < 4; r++) {
#pragma unroll
            for (int j = 0; j < 8; j++) {
                unsigned long long tmp;
                FFMA2(tmp, ar[r], zp[j], br[r]);
                FFMA2_ACC(acc[r][j], tmp, zp[j]);
            }
        }
    }

    float4 t34 = *(const float4*)(g_t3  + b * L_ + lbase);
    float4 mv4 = *(const float4*)(g_mlv + b * L_ + lbase);
    float t3a[4] = {t34.x, t34.y, t34.z, t34.w};
    float mva[4] = {mv4.x, mv4.y, mv4.z, mv4.w};
    unsigned long long c1 = pack2(-0.0125f, -0.0125f);
#pragma unroll
    for (int r = 0; r < 4; r++) {
        unsigned long long tp = pack2(t3a[r], t3a[r]);
        unsigned long long dp = pack2(-0.5f * mva[r], -0.5f * mva[r]);
        unsigned long long o[8];
#pragma unroll
        for (int j = 0; j < 8; j++) {
            unsigned long long mse;
            ADD2(mse, acc[r][j], tp);
            FFMA2(o[j], mse, c1, dp);
        }
        float* orow = lp_out + ((size_t)b * L_ + lbase + r) * T_ + t0 + tg * 16;
        ((ulonglong2*)orow)[0] = make_ulonglong2(o[0], o[1]);
        ((ulonglong2*)orow)[1] = make_ulonglong2(o[2], o[3]);
        ((ulonglong2*)orow)[2] = make_ulonglong2(o[4], o[5]);
        ((ulonglong2*)orow)[3] = make_ulonglong2(o[6], o[7]);
    }

    __threadfence();
    if (tid == 0) {
        atomicExch(&g_flag[b * NCH + c], 1);
        atomicAdd(&g_zc, 1);
    }
}

// ---- one DP step (t >= 1) ----
__device__ __forceinline__ void gstep(int t, float pre_a, float pre_b,
                                      int lane0, int lzero, int w,
                                      unsigned* D, float* b0h, float lpv,
                                      float* shv, int mlm1, int tlm1, int l,
                                      float& a, float& bt, float& oA, float& oB) {
    float sa = __shfl_up_sync(0xffffffffu, a, 1);
    float sb = __shfl_up_sync(0xffffffffu, bt, 1);
    float am = lane0 ? pre_a : sa;
    float bm = lane0 ? pre_b : sb;
    unsigned bal = __ballot_sync(0xffffffffu, bm > bt);
    if (lane0) D[(t - 1) * 8 + w] = bal;
    float d = a - am;
    float m = fmaxf(a, am);
    float an = m + __logf(1.0f + __expf(-fabsf(d))) + (lpv + 1e-7f);
    float bn = fmaxf(bt, bm) + lpv;
    if (t == mlm1 && l == tlm1) *shv = an;
    if (lzero) b0h[t] = bn;
    a = an; bt = bn; oA = an; oB = bn;
}

// ---- DP role: 8-warp feed-forward DP, 4-step grouped mailbox ----
__device__ void k2_role(int b, const float* __restrict__ lp,
                        const int* __restrict__ tlen, const int* __restrict__ mlen,
                        float* __restrict__ out_loss, float* __restrict__ out_align,
                        unsigned char* smraw) {
    unsigned* D = (unsigned*)smraw;
    float* b0h  = (float*)(smraw + SMB_B0H);
    int* path   = (int*)(smraw + SMB_PATH);
    float* shv  = (float*)(smraw + SMB_SHV);
    unsigned smbase = (unsigned)__cvta_generic_to_shared(smraw);
    unsigned mb     = smbase + SMB_MB;

    int l = threadIdx.x;
    int w = l >> 5, lane = l & 31;
    int lane0 = (lane == 0);
    int lzero = (l == 0);
    int ml = mlen[b], tl = tlen[b];
    int mlm1 = ml - 1, tlm1 = tl - 1;

    const float* p = lp + ((size_t)b * L_ + l) * T_;
    unsigned mb_self = mb + (unsigned)w * WSTRIDE;
    unsigned mb_src  = mb + (unsigned)(w - 1) * WSTRIDE;   // used only if w>=1

    // zero mailbox tags (whole region: 9600 uint4)
    {
        uint4* m4 = (uint4*)(smraw + SMB_MB);
        uint4 zz = make_uint4(0u, 0u, 0u, 0u);
        for (int i = l; i < 9600; i += 256) m4[i] = zz;
    }

    waitflag(b * NCH + 0);
    float4 vcur = *(const float4*)p;           // quad 0
    float a  = lzero ? vcur.x : -PADM;         // state t=0
    float bt = a;
    if (lzero) b0h[0] = bt;
    __syncthreads();                           // mailbox zero + init visible

    waitflag(b * NCH + 1);                     // covers chunk-0 prefetch window
    float4 vnext = *(const float4*)(p + 4);

    float ca = -PADM, cb = -PADM;              // carry: w-1 state at t=4k-1
    float pA[4], pB[4];

    // ---- group 0: steps t=1,2,3; entry0 = init state ----
    {
        pA[0] = a; pB[0] = bt;
        float e0a = -PADM, e0b = -PADM, e1a = -PADM, e1b = -PADM,
              e2a = -PADM, e2b = -PADM;
        if (w) {
            unsigned sl = mb_src;
            uint4 s0 = ldsv4v(sl);
            while (s0.x != 1u) s0 = ldsv4v(sl);
            uint4 s1 = ldsv4v(sl + 16u);
            uint4 s2 = ldsv4v(sl + 32u);
            e0a = __uint_as_float(s0.y); e0b = __uint_as_float(s0.z);
            e1a = __uint_as_float(s1.x); e1b = __uint_as_float(s1.y);
            e2a = __uint_as_float(s1.z); e2b = __uint_as_float(s1.w);
            ca  = __uint_as_float(s2.x); cb  = __uint_as_float(s2.y);
        }
        gstep(1, e0a, e0b, lane0, lzero, w, D, b0h, vcur.y, shv, mlm1, tlm1, l, a, bt, pA[1], pB[1]);
        gstep(2, e1a, e1b, lane0, lzero, w, D, b0h, vcur.z, shv, mlm1, tlm1, l, a, bt, pA[2], pB[2]);
        gstep(3, e2a, e2b, lane0, lzero, w, D, b0h, vcur.w, shv, mlm1, tlm1, l, a, bt, pA[3], pB[3]);
        if (lane == 31) {
            stsv4v(mb_self + 32u, make_uint4(__float_as_uint(pA[3]), __float_as_uint(pB[3]), 0u, 0u));
            stsv4v(mb_self + 16u, make_uint4(__float_as_uint(pA[1]), __float_as_uint(pB[1]),
                                             __float_as_uint(pA[2]), __float_as_uint(pB[2])));
            stsv4v(mb_self,       make_uint4(1u, __float_as_uint(pA[0]), __float_as_uint(pB[0]), 0u));
        }
        vcur = vnext; vnext = *(const float4*)(p + 8);
    }

    // ---- groups 1..399 ----
    for (int k = 1; k < 400; k++) {
        if ((k & 15) == 0) {
            int c2 = (k >> 4) + 1;
            waitflag(b * NCH + (c2 < NCH ? c2 : NCH - 1));
        }
        float4 vf = (k + 2 < 400) ? *(const float4*)(p + 4 * (k + 2)) : vcur;
        float e0a = -PADM, e0b = -PADM, e1a = -PADM, e1b = -PADM,
              e2a = -PADM, e2b = -PADM, nca = -PADM, ncb = -PADM;
        if (w) {
            unsigned sl = mb_src + (unsigned)k * 48u;
            uint4 s0 = ldsv4v(sl);
            while (s0.x != (unsigned)(k + 1)) s0 = ldsv4v(sl);
            uint4 s1 = ldsv4v(sl + 16u);
            uint4 s2 = ldsv4v(sl + 32u);
            e0a = __uint_as_float(s0.y); e0b = __uint_as_float(s0.z);
            e1a = __uint_as_float(s1.x); e1b = __uint_as_float(s1.y);
            e2a = __uint_as_float(s1.z); e2b = __uint_as_float(s1.w);
            nca = __uint_as_float(s2.x); ncb = __uint_as_float(s2.y);
        }
        int t0 = 4 * k;
        gstep(t0,     ca,  cb,  lane0, lzero, w, D, b0h, vcur.x, shv, mlm1, tlm1, l, a, bt, pA[0], pB[0]);
        gstep(t0 + 1, e0a, e0b, lane0, lzero, w, D, b0h, vcur.y, shv, mlm1, tlm1, l, a, bt, pA[1], pB[1]);
        gstep(t0 + 2, e1a, e1b, lane0, lzero, w, D, b0h, vcur.z, shv, mlm1, tlm1, l, a, bt, pA[2], pB[2]);
        gstep(t0 + 3, e2a, e2b, lane0, lzero, w, D, b0h, vcur.w, shv, mlm1, tlm1, l, a, bt, pA[3], pB[3]);
        ca = nca; cb = ncb;
        if (lane == 31) {
            unsigned sl = mb_self + (unsigned)k * 48u;
            stsv4v(sl + 32u, make_uint4(__float_as_uint(pA[3]), __float_as_uint(pB[3]), 0u, 0u));
            stsv4v(sl + 16u, make_uint4(__float_as_uint(pA[1]), __float_as_uint(pB[1]),
                                        __float_as_uint(pA[2]), __float_as_uint(pB[2])));
            stsv4v(sl,       make_uint4((unsigned)(k + 1), __float_as_uint(pA[0]),
                                        __float_as_uint(pB[0]), 0u));
        }
        vcur = vnext; vnext = vf;
    }

    // ---- column T-1 = 1599 decision bits (uses final carry) ----
    {
        float sb = __shfl_up_sync(0xffffffffu, bt, 1);
        float bm = lane0 ? cb : sb;               // w==0 lane0: -PADM carry, fixed below
        unsigned bal = __ballot_sync(0xffffffffu, bm > bt);
        if (lane0) D[(T_ - 1) * 8 + w] = bal;
    }
    __syncthreads();

    // ---- wrap fixup: bit0 of D[c*8] = (beta[255,c] > beta[0,c]) ----
    // beta[255,c] = warp7 mailbox slot (c>>2), entry (c&3)
    {
        const unsigned char* m7 = smraw + SMB_MB + 7 * WSTRIDE;
        for (int c = l; c < T_; c += 256) {
            int e = c & 3;
            int off = e ? (12 + 8 * e) : 8;
            float b255 = *(const float*)(m7 + (c >> 2) * 48 + off);
            unsigned wv = D[c * 8];
            wv = (wv & ~1u) | ((b255 > b0h[c]) ? 1u : 0u);
            D[c * 8] = wv;
        }
    }
    __syncthreads();

    // serial backtrack (exact emulation of reference relu/mod arithmetic)
    if (l == 0) {
        out_loss[b] = -(*shv) / (float)ml;
        int rows = tlm1, cols = mlm1;
        path[0] = rows;
        for (int k = 1; k < ml; k++) {
            int col = ((cols - 1) % T_ + T_) % T_;
            int br_ = rows & (L_ - 1);
            unsigned wv = D[col * 8 + (br_ >> 5)];
            int is_go = (wv >> (br_ & 31)) & 1;
            int tmp = rows - is_go + 1;
            rows = (tmp > 0 ? tmp : 0) - 1;
            cols = (cols > 0 ? cols : 0) - 1;
            path[k] = rows;
        }
        // all alignment-zeroing blocks must be done before one-hot writes
        volatile int* zc = &g_zc;
        while (*zc != B_ * NCH) {}
        __threadfence();
    }
    __syncthreads();

    // write one-hot ones: final[t] = onehot(path[ml-1-t]) for t < ml
    size_t abase = (size_t)b * T_ * L_;
    for (int t = l; t < ml; t += 256) {
        int r = path[mlm1 - t];
        if (r >= 0) out_align[abase + (size_t)t * L_ + r] = 1.0f;
    }
}

__global__ __launch_bounds__(256, 1) void k12_fused(const float* __restrict__ z,
                                                    float* __restrict__ lp_out,
                                                    const int* __restrict__ tlen,
                                                    const int* __restrict__ mlen,
                                                    float* __restrict__ out_loss,
                                                    float* __restrict__ out_align) {
    extern __shared__ unsigned char smraw[];
    if (blockIdx.x < B_) {
        k2_role(blockIdx.x, lp_out, tlen, mlen, out_loss, out_align, smraw);
    } else {
        int i = blockIdx.x - B_;
        int b = i & (B_ - 1);      // batch fastest -> every batch's chunk 0 in wave 1
        int c = i >> 5;
        k1_role(b, c, z, lp_out, out_align, smraw);
    }
}

// ---------------- launch ----------------
extern "C" void kernel_launch(void* const* d_in, const int* in_sizes, int n_in,
                              void* d_out, int out_size) {
    const float* mu_logvar = (const float*)d_in[0];   // [B, L, 2C]
    const float* z         = (const float*)d_in[1];   // [B, C, T]
    const int*   tlen      = (const int*)d_in[2];     // [B]
    const int*   mlen      = (const int*)d_in[3];     // [B]

    float* out       = (float*)d_out;
    float* out_loss  = out;                                   // [B]
    float* out_align = out + B_;                              // [B, T, L]
    float* out_lp    = out_align + (size_t)B_ * T_ * L_;      // [B, L, T]

    cudaFuncSetAttribute(k12_fused, cudaFuncAttributeMaxDynamicSharedMemorySize,
                         SMB_TOT);

    k0_coef<<<(B_ * L_) / 128, 128>>>(mu_logvar);
    k12_fused<<<B_ + B_ * NCH, 256, SMB_TOT>>>(z, out_lp, tlen, mlen,
                                               out_loss, out_align);
}